// round 14
// baseline (speedup 1.0000x reference)
#include <cuda_runtime.h>
#include <cuda_fp16.h>
#include <math.h>
#include <stdint.h>

#define NB 32
#define NL 128
#define NH 512
#define NG 2048
#define NV 32000
#define NE 128
#define NTOK 4096
#define NVT 250

// weight arena offsets (elements)
#define OFF_WIH0 0
#define OFF_WIH1 524288
#define OFF_W1   8912896
#define OFF_W2   9043968
#define WARENA   13139968

// ------------------ scratch ------------------
__device__ float g_wh[WARENA];                       // tf32 planes (dec_w2 only)
__device__ float g_wl[WARENA];
__device__ __align__(16) __half g_w16h[OFF_W2];      // fp16 planes: wih0, wih, dec_w1
__device__ __align__(16) __half g_w16l[OFF_W2];
__device__ __align__(16) __half g_whh16h[3 * 2 * NG * NH];
__device__ __align__(16) __half g_whh16l[3 * 2 * NG * NH];
__device__ __align__(16) __half g_a16h[NTOK * 1024]; // activation fp16 planes
__device__ __align__(16) __half g_a16l[NTOK * 1024];
__device__ float g_gx[2u * NTOK * NG];               // [d][t][g][b]
__device__ float g_hid[NTOK * 128];
__device__ float g_hidh[NTOK * 128];
__device__ float g_hidl[NTOK * 128];
__device__ __align__(16) __half g_hph16[2 * NB * NH];
__device__ __align__(16) __half g_hpl16[2 * NB * NH];
__device__ float g_part[2 * 4 * NG * NB];
__device__ float g_maskt[NL * NB];
__device__ float g_pmax[(size_t)NTOK * NVT];
__device__ float g_psum[(size_t)NTOK * NVT];
__device__ int   g_parg[(size_t)NTOK * NVT];
__device__ float g_nllw[NTOK];
__device__ float g_wtok[NTOK];
__device__ unsigned int g_barcnt2[2];

// ------------------ helpers ------------------
__device__ __forceinline__ float sigf(float x) {
    return 1.0f / (1.0f + __expf(-x));
}
__device__ __forceinline__ float tanhf_fast(float x) {
    float e = __expf(-2.0f * fabsf(x));
    float r = (1.0f - e) / (1.0f + e);
    return copysignf(r, x);
}

__device__ __forceinline__ void gridbar_d(int d) {
    __syncthreads();
    if (threadIdx.x == 0) {
        unsigned int* ctr = &g_barcnt2[d];
        unsigned int t;
        asm volatile("atom.add.release.gpu.u32 %0, [%1], 1;"
                     : "=r"(t) : "l"(ctr) : "memory");
        unsigned int need = ((t >> 6) + 1u) << 6;
        unsigned int cur;
        do {
            asm volatile("ld.acquire.gpu.u32 %0, [%1];"
                         : "=r"(cur) : "l"(ctr) : "memory");
        } while (cur < need);
    }
    __syncthreads();
}

__device__ __forceinline__ void tf32split(float x, float& hi, float& lo) {
    unsigned hb;
    asm("cvt.rna.tf32.f32 %0, %1;" : "=r"(hb) : "f"(x));
    float hf = __uint_as_float(hb);
    float l = x - hf;
    unsigned lb;
    asm("cvt.rna.tf32.f32 %0, %1;" : "=r"(lb) : "f"(l));
    hi = hf;
    lo = __uint_as_float(lb);
}

__device__ __forceinline__ void f16split(float v, __half& h, __half& l) {
    h = __float2half_rn(v);
    float r = v - __half2float(h);
    l = __float2half_rn(r * 4096.0f);
}

#define MMA_TF32(c, a, b)                                                     \
    asm volatile(                                                             \
        "mma.sync.aligned.m16n8k8.row.col.f32.tf32.tf32.f32 "                 \
        "{%0,%1,%2,%3}, {%4,%5,%6,%7}, {%8,%9}, {%0,%1,%2,%3};"               \
        : "+f"((c)[0]), "+f"((c)[1]), "+f"((c)[2]), "+f"((c)[3])              \
        : "r"((a)[0]), "r"((a)[1]), "r"((a)[2]), "r"((a)[3]),                 \
          "r"((b)[0]), "r"((b)[1]))

#define MMA_F16(c, a, b)                                                      \
    asm volatile(                                                             \
        "mma.sync.aligned.m16n8k16.row.col.f32.f16.f16.f32 "                  \
        "{%0,%1,%2,%3}, {%4,%5,%6,%7}, {%8,%9}, {%0,%1,%2,%3};"               \
        : "+f"((c)[0]), "+f"((c)[1]), "+f"((c)[2]), "+f"((c)[3])              \
        : "r"((a)[0]), "r"((a)[1]), "r"((a)[2]), "r"((a)[3]),                 \
          "r"((b)[0]), "r"((b)[1]))

__device__ __forceinline__ void cp16(uint32_t dst, const void* src) {
    asm volatile("cp.async.cg.shared.global [%0], [%1], 16;" :: "r"(dst), "l"(src));
}
#define CP_COMMIT() asm volatile("cp.async.commit_group;")
#define CP_WAIT1()  asm volatile("cp.async.wait_group 1;")
#define CP_WAIT0()  asm volatile("cp.async.wait_group 0;")

// tf32 gemm stage layout: 4 planes x 128 rows x 20 floats
#define PLANE 2560
#define STAGE 10240

// fp16 gemm stage layout (halves): Ah[128][40] Al[128][40] Bh[64][40] Bl[64][40]
#define H_AH 0
#define H_AL 5120
#define H_BH 10240
#define H_BL 12800
#define HSTG 15360

// scan smem layout (halves)
#define SW_H 0
#define SW_L 17408
#define SH_H 34816
#define SH_L 39168
#define SC_HALVES 43520

// ------------------ split kernels ------------------
__global__ __launch_bounds__(256) void k_split(const float* __restrict__ s,
                                               float* __restrict__ dh,
                                               float* __restrict__ dl, int n4) {
    int i = blockIdx.x * 256 + threadIdx.x;
    if (i < n4) {
        float4 v = ((const float4*)s)[i];
        float4 h4, l4;
        tf32split(v.x, h4.x, l4.x);
        tf32split(v.y, h4.y, l4.y);
        tf32split(v.z, h4.z, l4.z);
        tf32split(v.w, h4.w, l4.w);
        ((float4*)dh)[i] = h4;
        ((float4*)dl)[i] = l4;
    }
}

__global__ __launch_bounds__(256) void k_split16(const float* __restrict__ s,
                                                 __half* __restrict__ dh,
                                                 __half* __restrict__ dl, int n) {
    int i = blockIdx.x * 256 + threadIdx.x;
    if (i < n) {
        __half h, l;
        f16split(s[i], h, l);
        dh[i] = h;
        dl[i] = l;
    }
}

// ------------------ embedding (fp16 planes) ------------------
__global__ __launch_bounds__(256) void k_embed(const int* __restrict__ w,
                                               const float* __restrict__ emb) {
    int i = blockIdx.x * 256 + threadIdx.x;
    float v = emb[(size_t)w[i >> 7] * NE + (i & 127)];
    __half h, l;
    f16split(v, h, l);
    g_a16h[i] = h;
    g_a16l[i] = l;
}

// ------------------ zero h planes + barrier counters + mask transpose -----
__global__ __launch_bounds__(256) void k_zero(const float* __restrict__ mask) {
    int i = blockIdx.x * 256 + threadIdx.x;
    if (i < 2 * NB * NH) {
        g_hph16[i] = __float2half_rn(0.0f);
        g_hpl16[i] = __float2half_rn(0.0f);
    }
    if (i < NL * NB) {
        int t = i >> 5, b = i & 31;
        g_maskt[i] = mask[b * NL + t];
    }
    if (i < 2) g_barcnt2[i] = 0u;
}

// ------------------ fp16 dual-acc mma GEMM (gx layers + dec1) --------------
// Block 128m x 64n, 8 warps (2m x 4n), warp 64x16, mt=4, nt=2.
// result = acc1 + acc2/4096 + bias. gxt=1 -> gx transposed store [t][n][b].
// mode 2 -> relu + store g_hid + tf32 split planes.
__global__ __launch_bounds__(256) void k_gemm2h(const __half* __restrict__ Ahp,
                                                const __half* __restrict__ Alp,
                                                const __half* __restrict__ Whp,
                                                const __half* __restrict__ Wlp,
                                                const float* __restrict__ bias,
                                                float* __restrict__ C,
                                                int K, int N,
                                                long long wStr, long long bStr,
                                                long long cStr, int mode, int gxt) {
    extern __shared__ __half smh[];
    uint32_t smb = (uint32_t)__cvta_generic_to_shared(smh);

    int d = blockIdx.z;
    Whp += (size_t)d * wStr;
    Wlp += (size_t)d * wStr;
    bias += (size_t)d * bStr;
    C += (size_t)d * cStr;

    int tid = threadIdx.x;
    int m0 = blockIdx.y << 7;
    int n0 = blockIdx.x << 6;

    int wid = tid >> 5, lane = tid & 31;
    int gid = lane >> 2, t4 = lane & 3;
    int wm = (wid >> 2) << 6;     // 0 / 64
    int wnn = (wid & 3) << 4;     // 0,16,32,48

    float acc1[4][2][4], acc2[4][2][4];
#pragma unroll
    for (int mt = 0; mt < 4; mt++)
#pragma unroll
        for (int nt = 0; nt < 2; nt++)
#pragma unroll
            for (int r = 0; r < 4; r++) { acc1[mt][nt][r] = 0.0f; acc2[mt][nt][r] = 0.0f; }

    int T = K >> 5;

    // stage chunk cc into buffer bb: 1536 segments of 16B
    auto stage = [&](int cc, int bb) {
#pragma unroll
        for (int j = 0; j < 6; j++) {
            int s = tid + (j << 8);
            const __half* src;
            int off;
            if (s < 512) {
                int row = s >> 2, seg = s & 3;
                src = Ahp + (size_t)(m0 + row) * K + (cc << 5) + (seg << 3);
                off = H_AH + row * 40 + (seg << 3);
            } else if (s < 1024) {
                int r2 = s - 512;
                int row = r2 >> 2, seg = r2 & 3;
                src = Alp + (size_t)(m0 + row) * K + (cc << 5) + (seg << 3);
                off = H_AL + row * 40 + (seg << 3);
            } else if (s < 1280) {
                int r2 = s - 1024;
                int row = r2 >> 2, seg = r2 & 3;
                src = Whp + (size_t)(n0 + row) * K + (cc << 5) + (seg << 3);
                off = H_BH + row * 40 + (seg << 3);
            } else {
                int r2 = s - 1280;
                int row = r2 >> 2, seg = r2 & 3;
                src = Wlp + (size_t)(n0 + row) * K + (cc << 5) + (seg << 3);
                off = H_BL + row * 40 + (seg << 3);
            }
            cp16(smb + (uint32_t)((bb * HSTG + off) << 1), src);
        }
        CP_COMMIT();
    };

    stage(0, 0);
    for (int c = 0; c < T; c++) {
        int sb = c & 1;
        if (c + 1 < T) {
            stage(c + 1, sb ^ 1);
            CP_WAIT1();
        } else {
            CP_WAIT0();
        }
        __syncthreads();
        const __half* S = smh + sb * HSTG;

#pragma unroll
        for (int kk = 0; kk < 2; kk++) {
            int kb = (kk << 4) + (t4 << 1);
            unsigned ah[4][4], al[4][4];
#pragma unroll
            for (int mt = 0; mt < 4; mt++) {
                const __half* ar = S + H_AH + (wm + (mt << 4) + gid) * 40 + kb;
                const __half* al_ = S + H_AL + (wm + (mt << 4) + gid) * 40 + kb;
                ah[mt][0] = *(const unsigned*)ar;
                ah[mt][1] = *(const unsigned*)(ar + 8 * 40);
                ah[mt][2] = *(const unsigned*)(ar + 8);
                ah[mt][3] = *(const unsigned*)(ar + 8 * 40 + 8);
                al[mt][0] = *(const unsigned*)al_;
                al[mt][1] = *(const unsigned*)(al_ + 8 * 40);
                al[mt][2] = *(const unsigned*)(al_ + 8);
                al[mt][3] = *(const unsigned*)(al_ + 8 * 40 + 8);
            }
            unsigned bh[2][2], bl[2][2];
#pragma unroll
            for (int nt = 0; nt < 2; nt++) {
                const __half* br = S + H_BH + (wnn + (nt << 3) + gid) * 40 + kb;
                const __half* bl_ = S + H_BL + (wnn + (nt << 3) + gid) * 40 + kb;
                bh[nt][0] = *(const unsigned*)br;
                bh[nt][1] = *(const unsigned*)(br + 8);
                bl[nt][0] = *(const unsigned*)bl_;
                bl[nt][1] = *(const unsigned*)(bl_ + 8);
            }
#pragma unroll
            for (int mt = 0; mt < 4; mt++)
#pragma unroll
                for (int nt = 0; nt < 2; nt++) {
                    MMA_F16(acc1[mt][nt], ah[mt], bh[nt]);
                    MMA_F16(acc2[mt][nt], ah[mt], bl[nt]);
                    MMA_F16(acc2[mt][nt], al[mt], bh[nt]);
                }
        }
        __syncthreads();
    }

    const float sc = 1.0f / 4096.0f;
#pragma unroll
    for (int mt = 0; mt < 4; mt++) {
#pragma unroll
        for (int nt = 0; nt < 2; nt++) {
            int m = m0 + wm + (mt << 4) + gid;
            int n = n0 + wnn + (nt << 3) + (t4 << 1);
            float bv0 = bias[n], bv1 = bias[n + 1];
            float v0 = acc1[mt][nt][0] + acc2[mt][nt][0] * sc + bv0;
            float v1 = acc1[mt][nt][1] + acc2[mt][nt][1] * sc + bv1;
            float v2 = acc1[mt][nt][2] + acc2[mt][nt][2] * sc + bv0;
            float v3 = acc1[mt][nt][3] + acc2[mt][nt][3] * sc + bv1;
            if (mode) {
                v0 = fmaxf(v0, 0.0f); v1 = fmaxf(v1, 0.0f);
                v2 = fmaxf(v2, 0.0f); v3 = fmaxf(v3, 0.0f);
            }
            if (gxt) {
                int b = m >> 7;
                int tt = m & 127;
                C[((size_t)tt * NG + n) * NB + b] = v0;
                C[((size_t)tt * NG + n + 1) * NB + b] = v1;
                C[((size_t)(tt + 8) * NG + n) * NB + b] = v2;
                C[((size_t)(tt + 8) * NG + n + 1) * NB + b] = v3;
            } else {
                float2 p0 = {v0, v1};
                float2 p1 = {v2, v3};
                *(float2*)(C + (size_t)m * N + n) = p0;
                *(float2*)(C + (size_t)(m + 8) * N + n) = p1;
                if (mode == 2) {
                    float h, l;
                    size_t i0 = (size_t)m * N + n;
                    size_t i1 = (size_t)(m + 8) * N + n;
                    tf32split(v0, h, l); g_hidh[i0] = h;     g_hidl[i0] = l;
                    tf32split(v1, h, l); g_hidh[i0 + 1] = h; g_hidl[i0 + 1] = l;
                    tf32split(v2, h, l); g_hidh[i1] = h;     g_hidl[i1] = l;
                    tf32split(v3, h, l); g_hidh[i1 + 1] = h; g_hidl[i1 + 1] = l;
                }
            }
        }
    }
}

// ------------------ decoder2 mma (3xTF32, unchanged): logits + partials ----
__global__ __launch_bounds__(256) void k_dec2m(const float* __restrict__ b2) {
    extern __shared__ float smf[];
    uint32_t smb = (uint32_t)__cvta_generic_to_shared(smf);
    __shared__ float wmax[256];
    __shared__ int   warg[256];
    __shared__ float wsum[256];
    __shared__ float bmx[128];

    const float* Ahp = g_wh + OFF_W2;
    const float* Alp = g_wl + OFF_W2;

    int tid = threadIdx.x;
    int vt = blockIdx.x;
    int v0 = vt << 7;
    int n0 = blockIdx.y << 7;
    int lr = tid >> 2, lkq = (tid & 3) << 2;
    const int K = 128;

    const float* pA0h = Ahp + (size_t)(v0 + lr) * K + lkq;
    const float* pA1h = Ahp + (size_t)(v0 + lr + 64) * K + lkq;
    const float* pA0l = Alp + (size_t)(v0 + lr) * K + lkq;
    const float* pA1l = Alp + (size_t)(v0 + lr + 64) * K + lkq;
    const float* pB0h = g_hidh + (size_t)(n0 + lr) * K + lkq;
    const float* pB1h = g_hidh + (size_t)(n0 + lr + 64) * K + lkq;
    const float* pB0l = g_hidl + (size_t)(n0 + lr) * K + lkq;
    const float* pB1l = g_hidl + (size_t)(n0 + lr + 64) * K + lkq;

    uint32_t o0 = (uint32_t)((0 * PLANE + lr * 20 + lkq) * 4);
    uint32_t o1 = (uint32_t)((0 * PLANE + (lr + 64) * 20 + lkq) * 4);
    uint32_t o2 = (uint32_t)((1 * PLANE + lr * 20 + lkq) * 4);
    uint32_t o3 = (uint32_t)((1 * PLANE + (lr + 64) * 20 + lkq) * 4);
    uint32_t o4 = (uint32_t)((2 * PLANE + lr * 20 + lkq) * 4);
    uint32_t o5 = (uint32_t)((2 * PLANE + (lr + 64) * 20 + lkq) * 4);
    uint32_t o6 = (uint32_t)((3 * PLANE + lr * 20 + lkq) * 4);
    uint32_t o7 = (uint32_t)((3 * PLANE + (lr + 64) * 20 + lkq) * 4);

    int wid = tid >> 5, lane = tid & 31;
    int gid = lane >> 2, t4 = lane & 3;
    int wm = (wid >> 2) << 6;
    int wn = (wid & 3) << 5;

    float acc[4][4][4];
#pragma unroll
    for (int mt = 0; mt < 4; mt++)
#pragma unroll
        for (int nt = 0; nt < 4; nt++)
#pragma unroll
            for (int r = 0; r < 4; r++) acc[mt][nt][r] = 0.0f;

    const int T = 8;
    {
        uint32_t b = smb;
        cp16(b + o0, pA0h); cp16(b + o1, pA1h);
        cp16(b + o2, pA0l); cp16(b + o3, pA1l);
        cp16(b + o4, pB0h); cp16(b + o5, pB1h);
        cp16(b + o6, pB0l); cp16(b + o7, pB1l);
        CP_COMMIT();
    }
    for (int kt = 0; kt < T; kt++) {
        int s = kt & 1;
        if (kt + 1 < T) {
            int ko = (kt + 1) << 4;
            uint32_t b = smb + (uint32_t)((s ^ 1) * STAGE * 4);
            cp16(b + o0, pA0h + ko); cp16(b + o1, pA1h + ko);
            cp16(b + o2, pA0l + ko); cp16(b + o3, pA1l + ko);
            cp16(b + o4, pB0h + ko); cp16(b + o5, pB1h + ko);
            cp16(b + o6, pB0l + ko); cp16(b + o7, pB1l + ko);
            CP_COMMIT();
            CP_WAIT1();
        } else {
            CP_WAIT0();
        }
        __syncthreads();
        const float* S = smf + s * STAGE;
#pragma unroll
        for (int k8 = 0; k8 < 16; k8 += 8) {
            unsigned ah[4][4], al[4][4];
#pragma unroll
            for (int mt = 0; mt < 4; mt++) {
                int r0i = (wm + (mt << 4) + gid) * 20 + k8 + t4;
                int r1i = (wm + (mt << 4) + gid + 8) * 20 + k8 + t4;
                ah[mt][0] = __float_as_uint(S[r0i]);
                ah[mt][1] = __float_as_uint(S[r1i]);
                ah[mt][2] = __float_as_uint(S[r0i + 4]);
                ah[mt][3] = __float_as_uint(S[r1i + 4]);
                al[mt][0] = __float_as_uint(S[PLANE + r0i]);
                al[mt][1] = __float_as_uint(S[PLANE + r1i]);
                al[mt][2] = __float_as_uint(S[PLANE + r0i + 4]);
                al[mt][3] = __float_as_uint(S[PLANE + r1i + 4]);
            }
            unsigned bh[4][2], bl[4][2];
#pragma unroll
            for (int nt = 0; nt < 4; nt++) {
                int ci = (wn + (nt << 3) + gid) * 20 + k8 + t4;
                bh[nt][0] = __float_as_uint(S[2 * PLANE + ci]);
                bh[nt][1] = __float_as_uint(S[2 * PLANE + ci + 4]);
                bl[nt][0] = __float_as_uint(S[3 * PLANE + ci]);
                bl[nt][1] = __float_as_uint(S[3 * PLANE + ci + 4]);
            }
#pragma unroll
            for (int mt = 0; mt < 4; mt++)
#pragma unroll
                for (int nt = 0; nt < 4; nt++) {
                    MMA_TF32(acc[mt][nt], ah[mt], bh[nt]);
                    MMA_TF32(acc[mt][nt], ah[mt], bl[nt]);
                    MMA_TF32(acc[mt][nt], al[mt], bh[nt]);
                }
        }
        __syncthreads();
    }

    float bvv[4][2];
#pragma unroll
    for (int mt = 0; mt < 4; mt++) {
        bvv[mt][0] = b2[v0 + wm + (mt << 4) + gid];
        bvv[mt][1] = b2[v0 + wm + (mt << 4) + gid + 8];
    }
#pragma unroll
    for (int mt = 0; mt < 4; mt++)
#pragma unroll
        for (int nt = 0; nt < 4; nt++) {
            acc[mt][nt][0] += bvv[mt][0];
            acc[mt][nt][1] += bvv[mt][0];
            acc[mt][nt][2] += bvv[mt][1];
            acc[mt][nt][3] += bvv[mt][1];
        }

#pragma unroll
    for (int nt = 0; nt < 4; nt++) {
#pragma unroll
        for (int c = 0; c < 2; c++) {
            float lm = -1e30f;
            int la = 0;
#pragma unroll
            for (int mt = 0; mt < 4; mt++)
#pragma unroll
                for (int ro = 0; ro < 2; ro++) {
                    float lg = acc[mt][nt][ro * 2 + c];
                    if (lg > lm) {
                        lm = lg;
                        la = v0 + wm + (mt << 4) + gid + ro * 8;
                    }
                }
#pragma unroll
            for (int off = 4; off <= 16; off <<= 1) {
                float om = __shfl_xor_sync(0xffffffffu, lm, off);
                int oa = __shfl_xor_sync(0xffffffffu, la, off);
                if (om > lm || (om == lm && oa < la)) { lm = om; la = oa; }
            }
            if (gid == 0) {
                int tcol = wn + (nt << 3) + (t4 << 1) + c;
                wmax[(wm >> 6) * 128 + tcol] = lm;
                warg[(wm >> 6) * 128 + tcol] = la;
            }
        }
    }
    __syncthreads();
    float fm = 0.0f;
    int fa = 0;
    if (tid < 128) {
        float ma = wmax[tid], mb = wmax[128 + tid];
        if (mb > ma) { fm = mb; fa = warg[128 + tid]; }
        else { fm = ma; fa = warg[tid]; }
        bmx[tid] = fm;
    }
    __syncthreads();

#pragma unroll
    for (int nt = 0; nt < 4; nt++) {
#pragma unroll
        for (int c = 0; c < 2; c++) {
            int tcol = wn + (nt << 3) + (t4 << 1) + c;
            float mx = bmx[tcol];
            float s = 0.0f;
#pragma unroll
            for (int mt = 0; mt < 4; mt++)
#pragma unroll
                for (int ro = 0; ro < 2; ro++)
                    s += __expf(acc[mt][nt][ro * 2 + c] - mx);
#pragma unroll
            for (int off = 4; off <= 16; off <<= 1)
                s += __shfl_xor_sync(0xffffffffu, s, off);
            if (gid == 0) wsum[(wm >> 6) * 128 + tcol] = s;
        }
    }
    __syncthreads();
    if (tid < 128) {
        size_t tok = (size_t)(n0 + tid);
        g_pmax[tok * NVT + vt] = fm;
        g_parg[tok * NVT + vt] = fa;
        g_psum[tok * NVT + vt] = wsum[tid] + wsum[128 + tid];
    }
}

// ------------------ persistent BiLSTM scan (fp16 hi/lo mma, proven R13) ----
__global__ __launch_bounds__(256) void k_scan4(const float* __restrict__ gx,
                                               const __half* __restrict__ whh_h16,
                                               const __half* __restrict__ whh_l16) {
    extern __shared__ __half smh[];
    uint32_t smb = (uint32_t)__cvta_generic_to_shared(smh);

    int tid = threadIdx.x;
    int bid = blockIdx.x;
    int d = bid >> 6;
    int ks = (bid >> 4) & 3;
    int gt = bid & 15;
    int g0 = gt << 7;
    int k0 = ks << 7;

#pragma unroll
    for (int j = 0; j < 16; j++) {
        int idx = tid + (j << 8);
        int p = idx >> 11;
        int rem = idx & 2047;
        int row = rem >> 4;
        int seg = rem & 15;
        const __half* src = (p ? whh_l16 : whh_h16) +
                            (size_t)(d * NG + g0 + row) * NH + k0 + (seg << 3);
        uint4 v = __ldg((const uint4*)src);
        *(uint4*)&smh[(p ? SW_L : SW_H) + row * 136 + (seg << 3)] = v;
    }

    int wid = tid >> 5, lane = tid & 31;
    int gid = lane >> 2, t4 = lane & 3;
    int rowbase = wid << 4;

    int jt = bid & 63;
    int cb = tid & 31;
    int jl = tid >> 5;
    int cj = (jt << 3) + jl;
    float creg = 0.0f, hreg = 0.0f;

    const float* gxd = gx + (size_t)d * NL * NG * NB;

    __syncthreads();

    for (int s = 0; s < NL; s++) {
        int t = d ? (NL - 1 - s) : s;

        float gin[4];
        {
            const float* gxr = gxd + (size_t)t * NG * NB + cb;
#pragma unroll
            for (int gi = 0; gi < 4; gi++)
                gin[gi] = __ldg(&gxr[(size_t)(gi * NH + cj) * NB]);
        }
        float mt = g_maskt[t * NB + cb];

        {
#pragma unroll
            for (int j = 0; j < 4; j++) {
                int idx = tid + (j << 8);
                int p = idx >> 9;
                int rem = idx & 511;
                int row = rem >> 4;
                int seg = rem & 15;
                const __half* src = (p ? g_hpl16 : g_hph16) +
                                    (size_t)(d * NB + row) * NH + k0 + (seg << 3);
                uint32_t dst = smb + (uint32_t)(((p ? SH_L : SH_H) + row * 136 + (seg << 3)) << 1);
                cp16(dst, src);
            }
            CP_COMMIT();
            CP_WAIT0();
        }
        __syncthreads();

        float acc1[4][4], acc2[4][4];
#pragma unroll
        for (int nt = 0; nt < 4; nt++)
#pragma unroll
            for (int r = 0; r < 4; r++) { acc1[nt][r] = 0.0f; acc2[nt][r] = 0.0f; }

#pragma unroll
        for (int kk = 0; kk < 8; kk++) {
            int kb = (kk << 4) + (t4 << 1);
            const __half* wr = &smh[SW_H + (rowbase + gid) * 136 + kb];
            const __half* wl = &smh[SW_L + (rowbase + gid) * 136 + kb];
            unsigned ah[4], al[4];
            ah[0] = *(const unsigned*)wr;
            ah[1] = *(const unsigned*)(wr + 8 * 136);
            ah[2] = *(const unsigned*)(wr + 8);
            ah[3] = *(const unsigned*)(wr + 8 * 136 + 8);
            al[0] = *(const unsigned*)wl;
            al[1] = *(const unsigned*)(wl + 8 * 136);
            al[2] = *(const unsigned*)(wl + 8);
            al[3] = *(const unsigned*)(wl + 8 * 136 + 8);
#pragma unroll
            for (int nt = 0; nt < 4; nt++) {
                const __half* hr = &smh[SH_H + ((nt << 3) + gid) * 136 + kb];
                const __half* hl = &smh[SH_L + ((nt << 3) + gid) * 136 + kb];
                unsigned bh[2], bl[2];
                bh[0] = *(const unsigned*)hr;
                bh[1] = *(const unsigned*)(hr + 8);
                bl[0] = *(const unsigned*)hl;
                bl[1] = *(const unsigned*)(hl + 8);
                MMA_F16(acc1[nt], ah, bh);
                MMA_F16(acc2[nt], ah, bl);
                MMA_F16(acc2[nt], al, bh);
            }
        }

        {
            size_t pbase = ((size_t)(d * 4 + ks) * NG + g0) * NB;
            int grow = rowbase + gid;
            const float sc = 1.0f / 4096.0f;
#pragma unroll
            for (int nt = 0; nt < 4; nt++) {
                int b = (nt << 3) + (t4 << 1);
                float2 p0 = {acc1[nt][0] + acc2[nt][0] * sc,
                             acc1[nt][1] + acc2[nt][1] * sc};
                float2 p1 = {acc1[nt][2] + acc2[nt][2] * sc,
                             acc1[nt][3] + acc2[nt][3] * sc};
                *(float2*)&g_part[pbase + (size_t)grow * NB + b] = p0;
                *(float2*)&g_part[pbase + (size_t)(grow + 8) * NB + b] = p1;
            }
        }
        gridbar_d(d);

        {
            float gate[4];
#pragma unroll
            for (int gi = 0; gi < 4; gi++) {
                int g = gi * NH + cj;
                float v = gin[gi];
#pragma unroll
                for (int kss = 0; kss < 4; kss++)
                    v += __ldcg(&g_part[((size_t)(d * 4 + kss) * NG + g) * NB + cb]);
                gate[gi] = v;
            }
            float cn = sigf(gate[1]) * creg + sigf(gate[0]) * tanhf_fast(gate[2]);
            float hn = sigf(gate[3]) * tanhf_fast(cn);
            hreg = hreg + (hn - hreg) * mt;
            creg = creg + (cn - creg) * mt;
            __half hh16, hl16;
            f16split(hreg, hh16, hl16);
            size_t hidx = (size_t)(d * NB + cb) * NH + cj;
            g_hph16[hidx] = hh16;
            g_hpl16[hidx] = hl16;
            // fp16 split sequence output (next layer's A planes)
            size_t oidx = ((size_t)cb * NL + t) * 1024 + (d << 9) + cj;
            g_a16h[oidx] = hh16;
            g_a16l[oidx] = hl16;
        }
        gridbar_d(d);
    }
}

// ------------------ per-token combine ------------------
__global__ __launch_bounds__(256) void k_comb(const float* __restrict__ w2,
                                              const float* __restrict__ b2,
                                              const int* __restrict__ tgt,
                                              const float* __restrict__ cew,
                                              float* __restrict__ dout) {
    int warp = threadIdx.x >> 5, lane = threadIdx.x & 31;
    int m = blockIdx.x * 8 + warp;

    float lm = -1e30f, ls = 0.0f;
    int la = 0;
    for (int vt = lane; vt < NVT; vt += 32) {
        float tmx = g_pmax[(size_t)m * NVT + vt];
        float tsm = g_psum[(size_t)m * NVT + vt];
        int tag = g_parg[(size_t)m * NVT + vt];
        if (tmx > lm) {
            ls = ls * __expf(lm - tmx) + tsm;
            lm = tmx;
            la = tag;
        } else {
            ls += tsm * __expf(tmx - lm);
        }
    }
#pragma unroll
    for (int off = 16; off; off >>= 1) {
        float om = __shfl_down_sync(0xffffffffu, lm, off);
        float os = __shfl_down_sync(0xffffffffu, ls, off);
        int oa = __shfl_down_sync(0xffffffffu, la, off);
        float nm = fmaxf(lm, om);
        float ns = ls * __expf(lm - nm) + os * __expf(om - nm);
        int na = (om > lm) ? oa : ((om == lm && oa < la) ? oa : la);
        lm = nm; ls = ns; la = na;
    }

    int tg = tgt[m];
    float4 hv = *(const float4*)&g_hid[(size_t)m * 128 + lane * 4];
    float4 wv = *(const float4*)&w2[(size_t)tg * 128 + lane * 4];
    float dp = hv.x * wv.x + hv.y * wv.y + hv.z * wv.z + hv.w * wv.w;
#pragma unroll
    for (int off = 16; off; off >>= 1) dp += __shfl_down_sync(0xffffffffu, dp, off);

    if (lane == 0) {
        float logit_t = dp + b2[tg];
        float lse = lm + logf(ls);
        float nll = lse - logit_t;
        float w = cew[tg];
        g_nllw[m] = nll * w;
        g_wtok[m] = w;
        dout[1 + m] = (float)la;
    }
}

// ------------------ final loss reduce ------------------
__global__ __launch_bounds__(256) void k_loss(float* __restrict__ dout) {
    __shared__ float s1[256];
    __shared__ float s2[256];
    int tid = threadIdx.x;
    float a = 0.0f, b = 0.0f;
    for (int i = tid; i < NTOK; i += 256) { a += g_nllw[i]; b += g_wtok[i]; }
    s1[tid] = a; s2[tid] = b;
    __syncthreads();
    for (int off = 128; off; off >>= 1) {
        if (tid < off) { s1[tid] += s1[tid + off]; s2[tid] += s2[tid + off]; }
        __syncthreads();
    }
    if (tid == 0) dout[0] = s1[0] / s2[0];
}

// ------------------ launch ------------------
extern "C" void kernel_launch(void* const* d_in, const int* in_sizes, int n_in,
                              void* d_out, int out_size) {
    const int* inp_word = (const int*)d_in[0];
    const float* inp_mask = (const float*)d_in[1];
    const int* tgt_word = (const int*)d_in[3];
    const float* emb = (const float*)d_in[4];
    const float* w_ih0 = (const float*)d_in[5];
    const float* w_hh0 = (const float*)d_in[6];
    const float* b0 = (const float*)d_in[7];
    const float* w_ih = (const float*)d_in[8];
    const float* w_hh = (const float*)d_in[9];
    const float* bb = (const float*)d_in[10];
    const float* dec_w1 = (const float*)d_in[11];
    const float* dec_b1 = (const float*)d_in[12];
    const float* dec_w2 = (const float*)d_in[13];
    const float* dec_b2 = (const float*)d_in[14];
    const float* cew = (const float*)d_in[15];
    float* out = (float*)d_out;

    float *pgx, *phid, *pwh, *pwl;
    __half *pw16h, *pw16l, *pwhh16h, *pwhh16l, *pa16h, *pa16l;
    cudaGetSymbolAddress((void**)&pgx, g_gx);
    cudaGetSymbolAddress((void**)&phid, g_hid);
    cudaGetSymbolAddress((void**)&pwh, g_wh);
    cudaGetSymbolAddress((void**)&pwl, g_wl);
    cudaGetSymbolAddress((void**)&pw16h, g_w16h);
    cudaGetSymbolAddress((void**)&pw16l, g_w16l);
    cudaGetSymbolAddress((void**)&pwhh16h, g_whh16h);
    cudaGetSymbolAddress((void**)&pwhh16l, g_whh16l);
    cudaGetSymbolAddress((void**)&pa16h, g_a16h);
    cudaGetSymbolAddress((void**)&pa16l, g_a16l);

    const int gsm = 2 * STAGE * 4;        // 81920 B (dec2m)
    const int hsm = 2 * HSTG * 2;         // 61440 B (fp16 gemm)
    const int ssm = SC_HALVES * 2;        // 87040 B (scan)
    cudaFuncSetAttribute(k_gemm2h, cudaFuncAttributeMaxDynamicSharedMemorySize, hsm);
    cudaFuncSetAttribute(k_dec2m, cudaFuncAttributeMaxDynamicSharedMemorySize, gsm);
    cudaFuncSetAttribute(k_scan4, cudaFuncAttributeMaxDynamicSharedMemorySize, ssm);

    // 0. weight splits (fp16 for mma-h consumers, tf32 for dec2m) + embedding
    k_split16<<<2048, 256>>>(w_ih0, pw16h + OFF_WIH0, pw16l + OFF_WIH0, 524288);
    k_split16<<<32768, 256>>>(w_ih, pw16h + OFF_WIH1, pw16l + OFF_WIH1, 8388608);
    k_split16<<<512, 256>>>(dec_w1, pw16h + OFF_W1, pw16l + OFF_W1, 131072);
    k_split<<<4000, 256>>>(dec_w2, pwh + OFF_W2, pwl + OFF_W2, 4096000 / 4);
    k_split16<<<8192, 256>>>(w_hh0, pwhh16h, pwhh16l, 2 * NG * NH);
    k_split16<<<16384, 256>>>(w_hh, pwhh16h + 2 * NG * NH, pwhh16l + 2 * NG * NH,
                              4 * NG * NH);
    k_embed<<<(NTOK * NE) / 256, 256>>>(inp_word, emb);

    // layer 0
    k_gemm2h<<<dim3(NG / 64, NTOK / 128, 2), 256, hsm>>>(
        pa16h, pa16l, pw16h + OFF_WIH0, pw16l + OFF_WIH0, b0, pgx,
        NE, NG, (long long)NG * NE, NG, (long long)NL * NG * NB, 0, 1);
    k_zero<<<128, 256>>>(inp_mask);
    k_scan4<<<128, 256, ssm>>>(pgx, pwhh16h, pwhh16l);

    // layer 1
    k_gemm2h<<<dim3(NG / 64, NTOK / 128, 2), 256, hsm>>>(
        pa16h, pa16l, pw16h + OFF_WIH1, pw16l + OFF_WIH1, bb, pgx,
        1024, NG, (long long)NG * 1024, NG, (long long)NL * NG * NB, 0, 1);
    k_zero<<<128, 256>>>(inp_mask);
    k_scan4<<<128, 256, ssm>>>(pgx, pwhh16h + 2 * NG * NH, pwhh16l + 2 * NG * NH);

    // layer 2
    k_gemm2h<<<dim3(NG / 64, NTOK / 128, 2), 256, hsm>>>(
        pa16h, pa16l, pw16h + OFF_WIH1 + 4194304, pw16l + OFF_WIH1 + 4194304,
        bb + 2 * NG, pgx,
        1024, NG, (long long)NG * 1024, NG, (long long)NL * NG * NB, 0, 1);
    k_zero<<<128, 256>>>(inp_mask);
    k_scan4<<<128, 256, ssm>>>(pgx, pwhh16h + 4 * NG * NH, pwhh16l + 4 * NG * NH);

    // decoder layer 1 (relu, writes g_hid + tf32 split planes for dec2m)
    k_gemm2h<<<dim3(128 / 64, NTOK / 128, 1), 256, hsm>>>(
        pa16h, pa16l, pw16h + OFF_W1, pw16l + OFF_W1, dec_b1, phid,
        1024, 128, 0, 0, 0, 2, 0);

    // decoder layer 2 + fused online softmax partials
    k_dec2m<<<dim3(NVT, NTOK / 128), 256, gsm>>>(dec_b2);

    // per-token combine
    k_comb<<<NTOK / 8, 256>>>(dec_w2, dec_b2, tgt_word, cew, out);

    // loss reduce
    k_loss<<<1, 256>>>(out);
}

// round 15
// speedup vs baseline: 1.4443x; 1.4443x over previous
#include <cuda_runtime.h>
#include <cuda_fp16.h>
#include <math.h>
#include <stdint.h>

#define NB 32
#define NL 128
#define NH 512
#define NG 2048
#define NV 32000
#define NE 128
#define NTOK 4096
#define NVT 250

// weight arena offsets (elements)
#define OFF_WIH0 0
#define OFF_WIH1 524288
#define OFF_W1   8912896
#define OFF_W2   9043968
#define WARENA   13139968

// ------------------ scratch ------------------
__device__ float g_wh[WARENA];                       // tf32 planes (dec_w2 only)
__device__ float g_wl[WARENA];
__device__ __align__(16) __half g_w16h[OFF_W2];      // fp16 planes: wih0, wih, dec_w1
__device__ __align__(16) __half g_w16l[OFF_W2];
__device__ __align__(16) __half g_whh16h[3 * 2 * NG * NH];
__device__ __align__(16) __half g_whh16l[3 * 2 * NG * NH];
__device__ __align__(16) __half g_a16h[NTOK * 1024]; // activation fp16 planes
__device__ __align__(16) __half g_a16l[NTOK * 1024];
__device__ float g_gx[2u * NTOK * NG];               // [d][t][g][b]
__device__ float g_hid[NTOK * 128];
__device__ float g_hidh[NTOK * 128];
__device__ float g_hidl[NTOK * 128];
__device__ __align__(16) __half g_hph16[2 * NB * NH];
__device__ __align__(16) __half g_hpl16[2 * NB * NH];
__device__ float g_part[2 * 4 * NG * NB];
__device__ float g_maskt[NL * NB];
__device__ float g_pmax[(size_t)NTOK * NVT];
__device__ float g_psum[(size_t)NTOK * NVT];
__device__ int   g_parg[(size_t)NTOK * NVT];
__device__ float g_nllw[NTOK];
__device__ float g_wtok[NTOK];
__device__ unsigned int g_barcnt2[2];

// ------------------ helpers ------------------
__device__ __forceinline__ float sigf(float x) {
    return 1.0f / (1.0f + __expf(-x));
}
__device__ __forceinline__ float tanhf_fast(float x) {
    float e = __expf(-2.0f * fabsf(x));
    float r = (1.0f - e) / (1.0f + e);
    return copysignf(r, x);
}

__device__ __forceinline__ void gridbar_d(int d) {
    __syncthreads();
    if (threadIdx.x == 0) {
        unsigned int* ctr = &g_barcnt2[d];
        unsigned int t;
        asm volatile("atom.add.release.gpu.u32 %0, [%1], 1;"
                     : "=r"(t) : "l"(ctr) : "memory");
        unsigned int need = ((t >> 6) + 1u) << 6;
        unsigned int cur;
        do {
            asm volatile("ld.acquire.gpu.u32 %0, [%1];"
                         : "=r"(cur) : "l"(ctr) : "memory");
        } while (cur < need);
    }
    __syncthreads();
}

__device__ __forceinline__ void tf32split(float x, float& hi, float& lo) {
    unsigned hb;
    asm("cvt.rna.tf32.f32 %0, %1;" : "=r"(hb) : "f"(x));
    float hf = __uint_as_float(hb);
    float l = x - hf;
    unsigned lb;
    asm("cvt.rna.tf32.f32 %0, %1;" : "=r"(lb) : "f"(l));
    hi = hf;
    lo = __uint_as_float(lb);
}

__device__ __forceinline__ void f16split(float v, __half& h, __half& l) {
    h = __float2half_rn(v);
    float r = v - __half2float(h);
    l = __float2half_rn(r * 4096.0f);
}

#define MMA_TF32(c, a, b)                                                     \
    asm volatile(                                                             \
        "mma.sync.aligned.m16n8k8.row.col.f32.tf32.tf32.f32 "                 \
        "{%0,%1,%2,%3}, {%4,%5,%6,%7}, {%8,%9}, {%0,%1,%2,%3};"               \
        : "+f"((c)[0]), "+f"((c)[1]), "+f"((c)[2]), "+f"((c)[3])              \
        : "r"((a)[0]), "r"((a)[1]), "r"((a)[2]), "r"((a)[3]),                 \
          "r"((b)[0]), "r"((b)[1]))

#define MMA_F16(c, a, b)                                                      \
    asm volatile(                                                             \
        "mma.sync.aligned.m16n8k16.row.col.f32.f16.f16.f32 "                  \
        "{%0,%1,%2,%3}, {%4,%5,%6,%7}, {%8,%9}, {%0,%1,%2,%3};"               \
        : "+f"((c)[0]), "+f"((c)[1]), "+f"((c)[2]), "+f"((c)[3])              \
        : "r"((a)[0]), "r"((a)[1]), "r"((a)[2]), "r"((a)[3]),                 \
          "r"((b)[0]), "r"((b)[1]))

__device__ __forceinline__ void cp16(uint32_t dst, const void* src) {
    asm volatile("cp.async.cg.shared.global [%0], [%1], 16;" :: "r"(dst), "l"(src));
}
#define CP_COMMIT() asm volatile("cp.async.commit_group;")
#define CP_WAIT1()  asm volatile("cp.async.wait_group 1;")
#define CP_WAIT0()  asm volatile("cp.async.wait_group 0;")

// tf32 gemm stage layout (dec2m): 4 planes x 128 rows x 20 floats
#define PLANE 2560
#define STAGE 10240

// fp16 gemm stage layout (halves): 4 planes x 128 rows x 40 (32 data + pad)
#define HP_AH 0
#define HP_AL 5120
#define HP_BH 10240
#define HP_BL 15360
#define HSTG  20480

// scan smem layout (halves)
#define SW_H 0
#define SW_L 17408
#define SH_H 34816
#define SH_L 39168
#define SC_HALVES 43520

// ------------------ split kernels ------------------
__global__ __launch_bounds__(256) void k_split(const float* __restrict__ s,
                                               float* __restrict__ dh,
                                               float* __restrict__ dl, int n4) {
    int i = blockIdx.x * 256 + threadIdx.x;
    if (i < n4) {
        float4 v = ((const float4*)s)[i];
        float4 h4, l4;
        tf32split(v.x, h4.x, l4.x);
        tf32split(v.y, h4.y, l4.y);
        tf32split(v.z, h4.z, l4.z);
        tf32split(v.w, h4.w, l4.w);
        ((float4*)dh)[i] = h4;
        ((float4*)dl)[i] = l4;
    }
}

// vectorized fp16 split: 4 floats -> 4 hi halves + 4 lo halves per thread
__global__ __launch_bounds__(256) void k_split16(const float* __restrict__ s,
                                                 __half* __restrict__ dh,
                                                 __half* __restrict__ dl, int n4) {
    int i = blockIdx.x * 256 + threadIdx.x;
    if (i < n4) {
        float4 v = ((const float4*)s)[i];
        __half h0, h1, h2, h3, l0, l1, l2, l3;
        f16split(v.x, h0, l0);
        f16split(v.y, h1, l1);
        f16split(v.z, h2, l2);
        f16split(v.w, h3, l3);
        __half2 hh0 = __halves2half2(h0, h1);
        __half2 hh1 = __halves2half2(h2, h3);
        __half2 ll0 = __halves2half2(l0, l1);
        __half2 ll1 = __halves2half2(l2, l3);
        ((__half2*)dh)[i * 2] = hh0;
        ((__half2*)dh)[i * 2 + 1] = hh1;
        ((__half2*)dl)[i * 2] = ll0;
        ((__half2*)dl)[i * 2 + 1] = ll1;
    }
}

// ------------------ embedding (fp16 planes) ------------------
__global__ __launch_bounds__(256) void k_embed(const int* __restrict__ w,
                                               const float* __restrict__ emb) {
    int i = blockIdx.x * 256 + threadIdx.x;
    float v = emb[(size_t)w[i >> 7] * NE + (i & 127)];
    __half h, l;
    f16split(v, h, l);
    g_a16h[i] = h;
    g_a16l[i] = l;
}

// ------------------ zero h planes + barrier counters + mask transpose -----
__global__ __launch_bounds__(256) void k_zero(const float* __restrict__ mask) {
    int i = blockIdx.x * 256 + threadIdx.x;
    if (i < 2 * NB * NH) {
        g_hph16[i] = __float2half_rn(0.0f);
        g_hpl16[i] = __float2half_rn(0.0f);
    }
    if (i < NL * NB) {
        int t = i >> 5, b = i & 31;
        g_maskt[i] = mask[b * NL + t];
    }
    if (i < 2) g_barcnt2[i] = 0u;
}

// ------------------ fp16 dual-acc mma GEMM, 128x128 tile (R11 geometry) ----
// 8 warps (2m x 4n), warp 64x32. Chunk = 32 halves of K, double-buffered.
// result = acc1 + acc2/4096 + bias. gxt=1 -> transposed gx store [t][n][b].
// mode 2 -> relu + g_hid + tf32 split planes.
__global__ __launch_bounds__(256) void k_gemmh(const __half* __restrict__ Ahp,
                                               const __half* __restrict__ Alp,
                                               const __half* __restrict__ Whp,
                                               const __half* __restrict__ Wlp,
                                               const float* __restrict__ bias,
                                               float* __restrict__ C,
                                               int K, int N,
                                               long long wStr, long long bStr,
                                               long long cStr, int mode, int gxt) {
    extern __shared__ __half smh[];
    uint32_t smb = (uint32_t)__cvta_generic_to_shared(smh);

    int d = blockIdx.z;
    Whp += (size_t)d * wStr;
    Wlp += (size_t)d * wStr;
    bias += (size_t)d * bStr;
    C += (size_t)d * cStr;

    int tid = threadIdx.x;
    int m0 = blockIdx.y << 7, n0 = blockIdx.x << 7;

    int wid = tid >> 5, lane = tid & 31;
    int gid = lane >> 2, t4 = lane & 3;
    int wm = (wid >> 2) << 6;     // 0 / 64
    int wn = (wid & 3) << 5;      // 0,32,64,96

    float acc1[4][4][4], acc2[4][4][4];
#pragma unroll
    for (int mt = 0; mt < 4; mt++)
#pragma unroll
        for (int nt = 0; nt < 4; nt++)
#pragma unroll
            for (int r = 0; r < 4; r++) { acc1[mt][nt][r] = 0.0f; acc2[mt][nt][r] = 0.0f; }

    int T = K >> 5;

    // stage chunk cc into buffer bb: 2048 segments of 16B (8 per thread)
    auto stage = [&](int cc, int bb) {
#pragma unroll
        for (int j = 0; j < 8; j++) {
            int s = tid + (j << 8);        // 0..2047
            int p = s >> 9;                // plane 0..3
            int rem = s & 511;
            int row = rem >> 2;
            int seg = rem & 3;
            const __half* base = (p == 0) ? Ahp : (p == 1) ? Alp
                               : (p == 2) ? Whp : Wlp;
            int r0 = ((p < 2) ? m0 : n0) + row;
            const __half* src = base + (size_t)r0 * K + (cc << 5) + (seg << 3);
            uint32_t off = (uint32_t)((p * 5120 + row * 40 + (seg << 3)) << 1);
            cp16(smb + (uint32_t)(bb * HSTG * 2) + off, src);
        }
        CP_COMMIT();
    };

    stage(0, 0);
    for (int c = 0; c < T; c++) {
        int sb = c & 1;
        if (c + 1 < T) {
            stage(c + 1, sb ^ 1);
            CP_WAIT1();
        } else {
            CP_WAIT0();
        }
        __syncthreads();
        const __half* S = smh + sb * HSTG;

#pragma unroll
        for (int kk = 0; kk < 2; kk++) {
            int kb = (kk << 4) + (t4 << 1);
            unsigned ah[4][4], al[4][4];
#pragma unroll
            for (int mt = 0; mt < 4; mt++) {
                const __half* ar = S + HP_AH + (wm + (mt << 4) + gid) * 40 + kb;
                const __half* al_ = ar + (HP_AL - HP_AH);
                ah[mt][0] = *(const unsigned*)ar;
                ah[mt][1] = *(const unsigned*)(ar + 8 * 40);
                ah[mt][2] = *(const unsigned*)(ar + 8);
                ah[mt][3] = *(const unsigned*)(ar + 8 * 40 + 8);
                al[mt][0] = *(const unsigned*)al_;
                al[mt][1] = *(const unsigned*)(al_ + 8 * 40);
                al[mt][2] = *(const unsigned*)(al_ + 8);
                al[mt][3] = *(const unsigned*)(al_ + 8 * 40 + 8);
            }
            unsigned bh[4][2], bl[4][2];
#pragma unroll
            for (int nt = 0; nt < 4; nt++) {
                const __half* br = S + HP_BH + (wn + (nt << 3) + gid) * 40 + kb;
                const __half* bl_ = br + (HP_BL - HP_BH);
                bh[nt][0] = *(const unsigned*)br;
                bh[nt][1] = *(const unsigned*)(br + 8);
                bl[nt][0] = *(const unsigned*)bl_;
                bl[nt][1] = *(const unsigned*)(bl_ + 8);
            }
#pragma unroll
            for (int mt = 0; mt < 4; mt++)
#pragma unroll
                for (int nt = 0; nt < 4; nt++) {
                    MMA_F16(acc1[mt][nt], ah[mt], bh[nt]);
                    MMA_F16(acc2[mt][nt], ah[mt], bl[nt]);
                    MMA_F16(acc2[mt][nt], al[mt], bh[nt]);
                }
        }
        __syncthreads();
    }

    const float sc = 1.0f / 4096.0f;
#pragma unroll
    for (int mt = 0; mt < 4; mt++) {
#pragma unroll
        for (int nt = 0; nt < 4; nt++) {
            int m = m0 + wm + (mt << 4) + gid;
            int n = n0 + wn + (nt << 3) + (t4 << 1);
            float bv0 = bias[n], bv1 = bias[n + 1];
            float v0 = acc1[mt][nt][0] + acc2[mt][nt][0] * sc + bv0;
            float v1 = acc1[mt][nt][1] + acc2[mt][nt][1] * sc + bv1;
            float v2 = acc1[mt][nt][2] + acc2[mt][nt][2] * sc + bv0;
            float v3 = acc1[mt][nt][3] + acc2[mt][nt][3] * sc + bv1;
            if (mode) {
                v0 = fmaxf(v0, 0.0f); v1 = fmaxf(v1, 0.0f);
                v2 = fmaxf(v2, 0.0f); v3 = fmaxf(v3, 0.0f);
            }
            if (gxt) {
                int b = m >> 7;
                int tt = m & 127;
                C[((size_t)tt * NG + n) * NB + b] = v0;
                C[((size_t)tt * NG + n + 1) * NB + b] = v1;
                C[((size_t)(tt + 8) * NG + n) * NB + b] = v2;
                C[((size_t)(tt + 8) * NG + n + 1) * NB + b] = v3;
            } else {
                float2 p0 = {v0, v1};
                float2 p1 = {v2, v3};
                *(float2*)(C + (size_t)m * N + n) = p0;
                *(float2*)(C + (size_t)(m + 8) * N + n) = p1;
                if (mode == 2) {
                    float h, l;
                    size_t i0 = (size_t)m * N + n;
                    size_t i1 = (size_t)(m + 8) * N + n;
                    tf32split(v0, h, l); g_hidh[i0] = h;     g_hidl[i0] = l;
                    tf32split(v1, h, l); g_hidh[i0 + 1] = h; g_hidl[i0 + 1] = l;
                    tf32split(v2, h, l); g_hidh[i1] = h;     g_hidl[i1] = l;
                    tf32split(v3, h, l); g_hidh[i1 + 1] = h; g_hidl[i1 + 1] = l;
                }
            }
        }
    }
}

// ------------------ decoder2 mma (3xTF32, proven): logits + partials -------
__global__ __launch_bounds__(256) void k_dec2m(const float* __restrict__ b2) {
    extern __shared__ float smf[];
    uint32_t smb = (uint32_t)__cvta_generic_to_shared(smf);
    __shared__ float wmax[256];
    __shared__ int   warg[256];
    __shared__ float wsum[256];
    __shared__ float bmx[128];

    const float* Ahp = g_wh + OFF_W2;
    const float* Alp = g_wl + OFF_W2;

    int tid = threadIdx.x;
    int vt = blockIdx.x;
    int v0 = vt << 7;
    int n0 = blockIdx.y << 7;
    int lr = tid >> 2, lkq = (tid & 3) << 2;
    const int K = 128;

    const float* pA0h = Ahp + (size_t)(v0 + lr) * K + lkq;
    const float* pA1h = Ahp + (size_t)(v0 + lr + 64) * K + lkq;
    const float* pA0l = Alp + (size_t)(v0 + lr) * K + lkq;
    const float* pA1l = Alp + (size_t)(v0 + lr + 64) * K + lkq;
    const float* pB0h = g_hidh + (size_t)(n0 + lr) * K + lkq;
    const float* pB1h = g_hidh + (size_t)(n0 + lr + 64) * K + lkq;
    const float* pB0l = g_hidl + (size_t)(n0 + lr) * K + lkq;
    const float* pB1l = g_hidl + (size_t)(n0 + lr + 64) * K + lkq;

    uint32_t o0 = (uint32_t)((0 * PLANE + lr * 20 + lkq) * 4);
    uint32_t o1 = (uint32_t)((0 * PLANE + (lr + 64) * 20 + lkq) * 4);
    uint32_t o2 = (uint32_t)((1 * PLANE + lr * 20 + lkq) * 4);
    uint32_t o3 = (uint32_t)((1 * PLANE + (lr + 64) * 20 + lkq) * 4);
    uint32_t o4 = (uint32_t)((2 * PLANE + lr * 20 + lkq) * 4);
    uint32_t o5 = (uint32_t)((2 * PLANE + (lr + 64) * 20 + lkq) * 4);
    uint32_t o6 = (uint32_t)((3 * PLANE + lr * 20 + lkq) * 4);
    uint32_t o7 = (uint32_t)((3 * PLANE + (lr + 64) * 20 + lkq) * 4);

    int wid = tid >> 5, lane = tid & 31;
    int gid = lane >> 2, t4 = lane & 3;
    int wm = (wid >> 2) << 6;
    int wn = (wid & 3) << 5;

    float acc[4][4][4];
#pragma unroll
    for (int mt = 0; mt < 4; mt++)
#pragma unroll
        for (int nt = 0; nt < 4; nt++)
#pragma unroll
            for (int r = 0; r < 4; r++) acc[mt][nt][r] = 0.0f;

    const int T = 8;
    {
        uint32_t b = smb;
        cp16(b + o0, pA0h); cp16(b + o1, pA1h);
        cp16(b + o2, pA0l); cp16(b + o3, pA1l);
        cp16(b + o4, pB0h); cp16(b + o5, pB1h);
        cp16(b + o6, pB0l); cp16(b + o7, pB1l);
        CP_COMMIT();
    }
    for (int kt = 0; kt < T; kt++) {
        int s = kt & 1;
        if (kt + 1 < T) {
            int ko = (kt + 1) << 4;
            uint32_t b = smb + (uint32_t)((s ^ 1) * STAGE * 4);
            cp16(b + o0, pA0h + ko); cp16(b + o1, pA1h + ko);
            cp16(b + o2, pA0l + ko); cp16(b + o3, pA1l + ko);
            cp16(b + o4, pB0h + ko); cp16(b + o5, pB1h + ko);
            cp16(b + o6, pB0l + ko); cp16(b + o7, pB1l + ko);
            CP_COMMIT();
            CP_WAIT1();
        } else {
            CP_WAIT0();
        }
        __syncthreads();
        const float* S = smf + s * STAGE;
#pragma unroll
        for (int k8 = 0; k8 < 16; k8 += 8) {
            unsigned ah[4][4], al[4][4];
#pragma unroll
            for (int mt = 0; mt < 4; mt++) {
                int r0i = (wm + (mt << 4) + gid) * 20 + k8 + t4;
                int r1i = (wm + (mt << 4) + gid + 8) * 20 + k8 + t4;
                ah[mt][0] = __float_as_uint(S[r0i]);
                ah[mt][1] = __float_as_uint(S[r1i]);
                ah[mt][2] = __float_as_uint(S[r0i + 4]);
                ah[mt][3] = __float_as_uint(S[r1i + 4]);
                al[mt][0] = __float_as_uint(S[PLANE + r0i]);
                al[mt][1] = __float_as_uint(S[PLANE + r1i]);
                al[mt][2] = __float_as_uint(S[PLANE + r0i + 4]);
                al[mt][3] = __float_as_uint(S[PLANE + r1i + 4]);
            }
            unsigned bh[4][2], bl[4][2];
#pragma unroll
            for (int nt = 0; nt < 4; nt++) {
                int ci = (wn + (nt << 3) + gid) * 20 + k8 + t4;
                bh[nt][0] = __float_as_uint(S[2 * PLANE + ci]);
                bh[nt][1] = __float_as_uint(S[2 * PLANE + ci + 4]);
                bl[nt][0] = __float_as_uint(S[3 * PLANE + ci]);
                bl[nt][1] = __float_as_uint(S[3 * PLANE + ci + 4]);
            }
#pragma unroll
            for (int mt = 0; mt < 4; mt++)
#pragma unroll
                for (int nt = 0; nt < 4; nt++) {
                    MMA_TF32(acc[mt][nt], ah[mt], bh[nt]);
                    MMA_TF32(acc[mt][nt], ah[mt], bl[nt]);
                    MMA_TF32(acc[mt][nt], al[mt], bh[nt]);
                }
        }
        __syncthreads();
    }

    float bvv[4][2];
#pragma unroll
    for (int mt = 0; mt < 4; mt++) {
        bvv[mt][0] = b2[v0 + wm + (mt << 4) + gid];
        bvv[mt][1] = b2[v0 + wm + (mt << 4) + gid + 8];
    }
#pragma unroll
    for (int mt = 0; mt < 4; mt++)
#pragma unroll
        for (int nt = 0; nt < 4; nt++) {
            acc[mt][nt][0] += bvv[mt][0];
            acc[mt][nt][1] += bvv[mt][0];
            acc[mt][nt][2] += bvv[mt][1];
            acc[mt][nt][3] += bvv[mt][1];
        }

#pragma unroll
    for (int nt = 0; nt < 4; nt++) {
#pragma unroll
        for (int c = 0; c < 2; c++) {
            float lm = -1e30f;
            int la = 0;
#pragma unroll
            for (int mt = 0; mt < 4; mt++)
#pragma unroll
                for (int ro = 0; ro < 2; ro++) {
                    float lg = acc[mt][nt][ro * 2 + c];
                    if (lg > lm) {
                        lm = lg;
                        la = v0 + wm + (mt << 4) + gid + ro * 8;
                    }
                }
#pragma unroll
            for (int off = 4; off <= 16; off <<= 1) {
                float om = __shfl_xor_sync(0xffffffffu, lm, off);
                int oa = __shfl_xor_sync(0xffffffffu, la, off);
                if (om > lm || (om == lm && oa < la)) { lm = om; la = oa; }
            }
            if (gid == 0) {
                int tcol = wn + (nt << 3) + (t4 << 1) + c;
                wmax[(wm >> 6) * 128 + tcol] = lm;
                warg[(wm >> 6) * 128 + tcol] = la;
            }
        }
    }
    __syncthreads();
    float fm = 0.0f;
    int fa = 0;
    if (tid < 128) {
        float ma = wmax[tid], mb = wmax[128 + tid];
        if (mb > ma) { fm = mb; fa = warg[128 + tid]; }
        else { fm = ma; fa = warg[tid]; }
        bmx[tid] = fm;
    }
    __syncthreads();

#pragma unroll
    for (int nt = 0; nt < 4; nt++) {
#pragma unroll
        for (int c = 0; c < 2; c++) {
            int tcol = wn + (nt << 3) + (t4 << 1) + c;
            float mx = bmx[tcol];
            float s = 0.0f;
#pragma unroll
            for (int mt = 0; mt < 4; mt++)
#pragma unroll
                for (int ro = 0; ro < 2; ro++)
                    s += __expf(acc[mt][nt][ro * 2 + c] - mx);
#pragma unroll
            for (int off = 4; off <= 16; off <<= 1)
                s += __shfl_xor_sync(0xffffffffu, s, off);
            if (gid == 0) wsum[(wm >> 6) * 128 + tcol] = s;
        }
    }
    __syncthreads();
    if (tid < 128) {
        size_t tok = (size_t)(n0 + tid);
        g_pmax[tok * NVT + vt] = fm;
        g_parg[tok * NVT + vt] = fa;
        g_psum[tok * NVT + vt] = wsum[tid] + wsum[128 + tid];
    }
}

// ------------------ persistent BiLSTM scan (fp16 hi/lo mma, proven R13) ----
__global__ __launch_bounds__(256) void k_scan4(const float* __restrict__ gx,
                                               const __half* __restrict__ whh_h16,
                                               const __half* __restrict__ whh_l16) {
    extern __shared__ __half smh[];
    uint32_t smb = (uint32_t)__cvta_generic_to_shared(smh);

    int tid = threadIdx.x;
    int bid = blockIdx.x;
    int d = bid >> 6;
    int ks = (bid >> 4) & 3;
    int gt = bid & 15;
    int g0 = gt << 7;
    int k0 = ks << 7;

#pragma unroll
    for (int j = 0; j < 16; j++) {
        int idx = tid + (j << 8);
        int p = idx >> 11;
        int rem = idx & 2047;
        int row = rem >> 4;
        int seg = rem & 15;
        const __half* src = (p ? whh_l16 : whh_h16) +
                            (size_t)(d * NG + g0 + row) * NH + k0 + (seg << 3);
        uint4 v = __ldg((const uint4*)src);
        *(uint4*)&smh[(p ? SW_L : SW_H) + row * 136 + (seg << 3)] = v;
    }

    int wid = tid >> 5, lane = tid & 31;
    int gid = lane >> 2, t4 = lane & 3;
    int rowbase = wid << 4;

    int jt = bid & 63;
    int cb = tid & 31;
    int jl = tid >> 5;
    int cj = (jt << 3) + jl;
    float creg = 0.0f, hreg = 0.0f;

    const float* gxd = gx + (size_t)d * NL * NG * NB;

    __syncthreads();

    for (int s = 0; s < NL; s++) {
        int t = d ? (NL - 1 - s) : s;

        float gin[4];
        {
            const float* gxr = gxd + (size_t)t * NG * NB + cb;
#pragma unroll
            for (int gi = 0; gi < 4; gi++)
                gin[gi] = __ldg(&gxr[(size_t)(gi * NH + cj) * NB]);
        }
        float mt = g_maskt[t * NB + cb];

        {
#pragma unroll
            for (int j = 0; j < 4; j++) {
                int idx = tid + (j << 8);
                int p = idx >> 9;
                int rem = idx & 511;
                int row = rem >> 4;
                int seg = rem & 15;
                const __half* src = (p ? g_hpl16 : g_hph16) +
                                    (size_t)(d * NB + row) * NH + k0 + (seg << 3);
                uint32_t dst = smb + (uint32_t)(((p ? SH_L : SH_H) + row * 136 + (seg << 3)) << 1);
                cp16(dst, src);
            }
            CP_COMMIT();
            CP_WAIT0();
        }
        __syncthreads();

        float acc1[4][4], acc2[4][4];
#pragma unroll
        for (int nt = 0; nt < 4; nt++)
#pragma unroll
            for (int r = 0; r < 4; r++) { acc1[nt][r] = 0.0f; acc2[nt][r] = 0.0f; }

#pragma unroll
        for (int kk = 0; kk < 8; kk++) {
            int kb = (kk << 4) + (t4 << 1);
            const __half* wr = &smh[SW_H + (rowbase + gid) * 136 + kb];
            const __half* wl = &smh[SW_L + (rowbase + gid) * 136 + kb];
            unsigned ah[4], al[4];
            ah[0] = *(const unsigned*)wr;
            ah[1] = *(const unsigned*)(wr + 8 * 136);
            ah[2] = *(const unsigned*)(wr + 8);
            ah[3] = *(const unsigned*)(wr + 8 * 136 + 8);
            al[0] = *(const unsigned*)wl;
            al[1] = *(const unsigned*)(wl + 8 * 136);
            al[2] = *(const unsigned*)(wl + 8);
            al[3] = *(const unsigned*)(wl + 8 * 136 + 8);
#pragma unroll
            for (int nt = 0; nt < 4; nt++) {
                const __half* hr = &smh[SH_H + ((nt << 3) + gid) * 136 + kb];
                const __half* hl = &smh[SH_L + ((nt << 3) + gid) * 136 + kb];
                unsigned bh[2], bl[2];
                bh[0] = *(const unsigned*)hr;
                bh[1] = *(const unsigned*)(hr + 8);
                bl[0] = *(const unsigned*)hl;
                bl[1] = *(const unsigned*)(hl + 8);
                MMA_F16(acc1[nt], ah, bh);
                MMA_F16(acc2[nt], ah, bl);
                MMA_F16(acc2[nt], al, bh);
            }
        }

        {
            size_t pbase = ((size_t)(d * 4 + ks) * NG + g0) * NB;
            int grow = rowbase + gid;
            const float sc = 1.0f / 4096.0f;
#pragma unroll
            for (int nt = 0; nt < 4; nt++) {
                int b = (nt << 3) + (t4 << 1);
                float2 p0 = {acc1[nt][0] + acc2[nt][0] * sc,
                             acc1[nt][1] + acc2[nt][1] * sc};
                float2 p1 = {acc1[nt][2] + acc2[nt][2] * sc,
                             acc1[nt][3] + acc2[nt][3] * sc};
                *(float2*)&g_part[pbase + (size_t)grow * NB + b] = p0;
                *(float2*)&g_part[pbase + (size_t)(grow + 8) * NB + b] = p1;
            }
        }
        gridbar_d(d);

        {
            float gate[4];
#pragma unroll
            for (int gi = 0; gi < 4; gi++) {
                int g = gi * NH + cj;
                float v = gin[gi];
#pragma unroll
                for (int kss = 0; kss < 4; kss++)
                    v += __ldcg(&g_part[((size_t)(d * 4 + kss) * NG + g) * NB + cb]);
                gate[gi] = v;
            }
            float cn = sigf(gate[1]) * creg + sigf(gate[0]) * tanhf_fast(gate[2]);
            float hn = sigf(gate[3]) * tanhf_fast(cn);
            hreg = hreg + (hn - hreg) * mt;
            creg = creg + (cn - creg) * mt;
            __half hh16, hl16;
            f16split(hreg, hh16, hl16);
            size_t hidx = (size_t)(d * NB + cb) * NH + cj;
            g_hph16[hidx] = hh16;
            g_hpl16[hidx] = hl16;
            size_t oidx = ((size_t)cb * NL + t) * 1024 + (d << 9) + cj;
            g_a16h[oidx] = hh16;
            g_a16l[oidx] = hl16;
        }
        gridbar_d(d);
    }
}

// ------------------ per-token combine ------------------
__global__ __launch_bounds__(256) void k_comb(const float* __restrict__ w2,
                                              const float* __restrict__ b2,
                                              const int* __restrict__ tgt,
                                              const float* __restrict__ cew,
                                              float* __restrict__ dout) {
    int warp = threadIdx.x >> 5, lane = threadIdx.x & 31;
    int m = blockIdx.x * 8 + warp;

    float lm = -1e30f, ls = 0.0f;
    int la = 0;
    for (int vt = lane; vt < NVT; vt += 32) {
        float tmx = g_pmax[(size_t)m * NVT + vt];
        float tsm = g_psum[(size_t)m * NVT + vt];
        int tag = g_parg[(size_t)m * NVT + vt];
        if (tmx > lm) {
            ls = ls * __expf(lm - tmx) + tsm;
            lm = tmx;
            la = tag;
        } else {
            ls += tsm * __expf(tmx - lm);
        }
    }
#pragma unroll
    for (int off = 16; off; off >>= 1) {
        float om = __shfl_down_sync(0xffffffffu, lm, off);
        float os = __shfl_down_sync(0xffffffffu, ls, off);
        int oa = __shfl_down_sync(0xffffffffu, la, off);
        float nm = fmaxf(lm, om);
        float ns = ls * __expf(lm - nm) + os * __expf(om - nm);
        int na = (om > lm) ? oa : ((om == lm && oa < la) ? oa : la);
        lm = nm; ls = ns; la = na;
    }

    int tg = tgt[m];
    float4 hv = *(const float4*)&g_hid[(size_t)m * 128 + lane * 4];
    float4 wv = *(const float4*)&w2[(size_t)tg * 128 + lane * 4];
    float dp = hv.x * wv.x + hv.y * wv.y + hv.z * wv.z + hv.w * wv.w;
#pragma unroll
    for (int off = 16; off; off >>= 1) dp += __shfl_down_sync(0xffffffffu, dp, off);

    if (lane == 0) {
        float logit_t = dp + b2[tg];
        float lse = lm + logf(ls);
        float nll = lse - logit_t;
        float w = cew[tg];
        g_nllw[m] = nll * w;
        g_wtok[m] = w;
        dout[1 + m] = (float)la;
    }
}

// ------------------ final loss reduce ------------------
__global__ __launch_bounds__(256) void k_loss(float* __restrict__ dout) {
    __shared__ float s1[256];
    __shared__ float s2[256];
    int tid = threadIdx.x;
    float a = 0.0f, b = 0.0f;
    for (int i = tid; i < NTOK; i += 256) { a += g_nllw[i]; b += g_wtok[i]; }
    s1[tid] = a; s2[tid] = b;
    __syncthreads();
    for (int off = 128; off; off >>= 1) {
        if (tid < off) { s1[tid] += s1[tid + off]; s2[tid] += s2[tid + off]; }
        __syncthreads();
    }
    if (tid == 0) dout[0] = s1[0] / s2[0];
}

// ------------------ launch ------------------
extern "C" void kernel_launch(void* const* d_in, const int* in_sizes, int n_in,
                              void* d_out, int out_size) {
    const int* inp_word = (const int*)d_in[0];
    const float* inp_mask = (const float*)d_in[1];
    const int* tgt_word = (const int*)d_in[3];
    const float* emb = (const float*)d_in[4];
    const float* w_ih0 = (const float*)d_in[5];
    const float* w_hh0 = (const float*)d_in[6];
    const float* b0 = (const float*)d_in[7];
    const float* w_ih = (const float*)d_in[8];
    const float* w_hh = (const float*)d_in[9];
    const float* bb = (const float*)d_in[10];
    const float* dec_w1 = (const float*)d_in[11];
    const float* dec_b1 = (const float*)d_in[12];
    const float* dec_w2 = (const float*)d_in[13];
    const float* dec_b2 = (const float*)d_in[14];
    const float* cew = (const float*)d_in[15];
    float* out = (float*)d_out;

    float *pgx, *phid, *pwh, *pwl;
    __half *pw16h, *pw16l, *pwhh16h, *pwhh16l, *pa16h, *pa16l;
    cudaGetSymbolAddress((void**)&pgx, g_gx);
    cudaGetSymbolAddress((void**)&phid, g_hid);
    cudaGetSymbolAddress((void**)&pwh, g_wh);
    cudaGetSymbolAddress((void**)&pwl, g_wl);
    cudaGetSymbolAddress((void**)&pw16h, g_w16h);
    cudaGetSymbolAddress((void**)&pw16l, g_w16l);
    cudaGetSymbolAddress((void**)&pwhh16h, g_whh16h);
    cudaGetSymbolAddress((void**)&pwhh16l, g_whh16l);
    cudaGetSymbolAddress((void**)&pa16h, g_a16h);
    cudaGetSymbolAddress((void**)&pa16l, g_a16l);

    const int gsm = 2 * STAGE * 4;        // 81920 B (dec2m)
    const int hsm = 2 * HSTG * 2;         // 81920 B (fp16 gemm)
    const int ssm = SC_HALVES * 2;        // 87040 B (scan)
    cudaFuncSetAttribute(k_gemmh, cudaFuncAttributeMaxDynamicSharedMemorySize, hsm);
    cudaFuncSetAttribute(k_dec2m, cudaFuncAttributeMaxDynamicSharedMemorySize, gsm);
    cudaFuncSetAttribute(k_scan4, cudaFuncAttributeMaxDynamicSharedMemorySize, ssm);

    // 0. weight splits (fp16 vectorized; tf32 only for dec_w2) + embedding
    k_split16<<<512, 256>>>(w_ih0, pw16h + OFF_WIH0, pw16l + OFF_WIH0, 524288 / 4);
    k_split16<<<8192, 256>>>(w_ih, pw16h + OFF_WIH1, pw16l + OFF_WIH1, 8388608 / 4);
    k_split16<<<128, 256>>>(dec_w1, pw16h + OFF_W1, pw16l + OFF_W1, 131072 / 4);
    k_split<<<4000, 256>>>(dec_w2, pwh + OFF_W2, pwl + OFF_W2, 4096000 / 4);
    k_split16<<<2048, 256>>>(w_hh0, pwhh16h, pwhh16l, 2097152 / 4);
    k_split16<<<4096, 256>>>(w_hh, pwhh16h + 2 * NG * NH, pwhh16l + 2 * NG * NH,
                             4194304 / 4);
    k_embed<<<(NTOK * NE) / 256, 256>>>(inp_word, emb);

    // layer 0
    k_gemmh<<<dim3(NG / 128, NTOK / 128, 2), 256, hsm>>>(
        pa16h, pa16l, pw16h + OFF_WIH0, pw16l + OFF_WIH0, b0, pgx,
        NE, NG, (long long)NG * NE, NG, (long long)NL * NG * NB, 0, 1);
    k_zero<<<128, 256>>>(inp_mask);
    k_scan4<<<128, 256, ssm>>>(pgx, pwhh16h, pwhh16l);

    // layer 1
    k_gemmh<<<dim3(NG / 128, NTOK / 128, 2), 256, hsm>>>(
        pa16h, pa16l, pw16h + OFF_WIH1, pw16l + OFF_WIH1, bb, pgx,
        1024, NG, (long long)NG * 1024, NG, (long long)NL * NG * NB, 0, 1);
    k_zero<<<128, 256>>>(inp_mask);
    k_scan4<<<128, 256, ssm>>>(pgx, pwhh16h + 2 * NG * NH, pwhh16l + 2 * NG * NH);

    // layer 2
    k_gemmh<<<dim3(NG / 128, NTOK / 128, 2), 256, hsm>>>(
        pa16h, pa16l, pw16h + OFF_WIH1 + 4194304, pw16l + OFF_WIH1 + 4194304,
        bb + 2 * NG, pgx,
        1024, NG, (long long)NG * 1024, NG, (long long)NL * NG * NB, 0, 1);
    k_zero<<<128, 256>>>(inp_mask);
    k_scan4<<<128, 256, ssm>>>(pgx, pwhh16h + 4 * NG * NH, pwhh16l + 4 * NG * NH);

    // decoder layer 1 (relu, writes g_hid + tf32 split planes for dec2m)
    k_gemmh<<<dim3(1, NTOK / 128, 1), 256, hsm>>>(
        pa16h, pa16l, pw16h + OFF_W1, pw16l + OFF_W1, dec_b1, phid,
        1024, 128, 0, 0, 0, 2, 0);

    // decoder layer 2 + fused online softmax partials
    k_dec2m<<<dim3(NVT, NTOK / 128), 256, gsm>>>(dec_b2);

    // per-token combine
    k_comb<<<NTOK / 8, 256>>>(dec_w2, dec_b2, tgt_word, cew, out);

    // loss reduce
    k_loss<<<1, 256>>>(out);
}